// round 13
// baseline (speedup 1.0000x reference)
#include <cuda_runtime.h>
#include <cuda_fp16.h>
#include <cstdint>

#define REL_CONTEXT 0.2f

// ---------------- problem dims (fixed) ----------------
#define NROWS 8192
#define DIM   2048
#define BM    128
#define BN    128
#define NSTEP (DIM / 16)      // 128 k-steps of 16

// ---------------- scratch: BOTH operands fragment-major fp16 ----------------
// A: group (step, tm) at ((step*512 + tm) * 512) bytes; tm = m16 tile (0..511)
//    lane l holds 16B = {a0,a1,a2,a3}: a0=(r0,c0..c0+1) a1=(r0+8,c0..) a2=(r0,c0+8..) a3=(r0+8,c0+8..)
//    r0 = tm*16 + l/4, c0 = step*16 + (l%4)*2
__device__ __align__(128) uint32_t g_AhF[(size_t)NROWS * DIM / 2];
// W: round-9 layout: group = ((ch*16+cb)*4+wN)*4+ks, 1024B each, lane*32 within
__device__ __align__(128) uint32_t g_WhF[(size_t)DIM * DIM / 2];
__device__ float g_zeta;

// ---------------- PTX helpers (base-target only) ----------------
#define MMA_F16(d, a, b) \
    asm volatile("mma.sync.aligned.m16n8k16.row.col.f32.f16.f16.f32 " \
                 "{%0,%1,%2,%3}, {%4,%5,%6,%7}, {%8,%9}, {%0,%1,%2,%3};" \
                 : "+f"((d)[0]), "+f"((d)[1]), "+f"((d)[2]), "+f"((d)[3]) \
                 : "r"((a)[0]), "r"((a)[1]), "r"((a)[2]), "r"((a)[3]), \
                   "r"((b)[0]), "r"((b)[1]))

__device__ __forceinline__ uint32_t pack_h2(float a, float b) {
    __half ha = __float2half_rn(a), hb = __float2half_rn(b);
    return (uint32_t)*(uint16_t*)&ha | ((uint32_t)*(uint16_t*)&hb << 16);
}

// ---------------- merged prep kernel ----------------
// blocks [0, ABLK)              : x+emb -> A fragments (16 groups/block)
// blocks [ABLK, ABLK+WFBLK)     : Wt -> W fragments (8 groups/block, round-9)
// block  ABLK+WFBLK             : zeta
#define AGRPS (512 * 128)       // 65536 A fragment groups (tm x step)
#define ABLK  (AGRPS / 16)      // 4096 blocks
#define WGRPS (32 * 16 * 4 * 4) // 8192 W fragment groups
#define WFBLK (WGRPS / 8)       // 1024 blocks
__global__ void prep_all(const float* __restrict__ x,
                         const int* __restrict__ ids,
                         const float* __restrict__ emb,
                         const float* __restrict__ Wt,
                         const float* __restrict__ Wrc,
                         const float* __restrict__ brc) {
    const int b = blockIdx.x;
    const int c4 = threadIdx.x;           // 512 threads
    if (b < ABLK) {
        const int g = b * 16 + (c4 >> 5);       // group: tm = g & 511, step = g >> 9
        const int lane = c4 & 31;
        const int tm = g & 511;
        const int step = g >> 9;
        const int r0 = tm * 16 + (lane >> 2);
        const int r1 = r0 + 8;
        const int c0 = step * 16 + (lane & 3) * 2;
        const int id0 = ids[r0];
        const int id1 = ids[r1];
        float2 x00 = *(const float2*)(x + (size_t)r0 * DIM + c0);
        float2 x10 = *(const float2*)(x + (size_t)r1 * DIM + c0);
        float2 x01 = *(const float2*)(x + (size_t)r0 * DIM + c0 + 8);
        float2 x11 = *(const float2*)(x + (size_t)r1 * DIM + c0 + 8);
        float2 e00 = *(const float2*)(emb + (size_t)id0 * DIM + c0);
        float2 e10 = *(const float2*)(emb + (size_t)id1 * DIM + c0);
        float2 e01 = *(const float2*)(emb + (size_t)id0 * DIM + c0 + 8);
        float2 e11 = *(const float2*)(emb + (size_t)id1 * DIM + c0 + 8);
        uint4 o;
        o.x = pack_h2(x00.x + e00.x, x00.y + e00.y);   // a0
        o.y = pack_h2(x10.x + e10.x, x10.y + e10.y);   // a1
        o.z = pack_h2(x01.x + e01.x, x01.y + e01.y);   // a2
        o.w = pack_h2(x11.x + e11.x, x11.y + e11.y);   // a3
        *(uint4*)((char*)g_AhF + (size_t)g * 512 + lane * 16) = o;
    } else if (b < ABLK + WFBLK) {
        const int g = (b - ABLK) * 8 + (c4 >> 6);
        const int t = c4 & 63;
        const int ks = g & 3;
        const int wN = (g >> 2) & 3;
        const int cb = (g >> 4) & 15;
        const int ch = g >> 8;
        const int lane = t >> 1;
        const int half = t & 1;
        const int n0 = cb * 128 + wN * 32 + half * 16 + (lane >> 2);
        const int k0 = ch * 64 + ks * 16 + (lane & 3) * 2;
        uint32_t w[4];
        #pragma unroll
        for (int dq = 0; dq < 2; dq++) {
            #pragma unroll
            for (int i = 0; i < 2; i++) {
                const float* p = Wt + (size_t)(n0 + dq * 8) * DIM + k0 + i * 8;
                float2 wv = *(const float2*)p;
                w[dq * 2 + i] = pack_h2(wv.x, wv.y);
            }
        }
        *(uint4*)((char*)g_WhF + (size_t)g * 1024 + lane * 32 + half * 16) =
            make_uint4(w[0], w[1], w[2], w[3]);
    } else {
        __shared__ float red[32];
        float s = 0.f;
        for (int i = c4; i < DIM; i += 512) s += Wrc[i];
        #pragma unroll
        for (int o = 16; o > 0; o >>= 1) s += __shfl_down_sync(0xffffffffu, s, o);
        if ((c4 & 31) == 0) red[c4 >> 5] = s;
        __syncthreads();
        if (c4 < 32) {
            float v = (c4 < 16) ? red[c4] : 0.f;
            #pragma unroll
            for (int o = 8; o > 0; o >>= 1) v += __shfl_down_sync(0xffffffffu, v, o);
            if (c4 == 0)
                g_zeta = 1.f / (1.f + expf(-(REL_CONTEXT * v + brc[0])));
        }
    }
}

// ---------------- main MMA kernel: zero-sync, all-LDG fragments ----------
__global__ __launch_bounds__(256, 2)
void redaf_mma(const float* __restrict__ mw,
               const float* __restrict__ bt,
               float* __restrict__ out) {
    const int tid = threadIdx.x;
    const int wid = tid >> 5;
    const int lid = tid & 31;

    const int cb      = blockIdx.x;        // col block (BN=128)
    const int colBase = cb * BN;
    const int rowBase = blockIdx.y * BM;

    // warp grid 2(M) x 4(N); warp tile 64x32
    const int warpM = wid & 1;
    const int warpN = wid >> 1;
    const int tm0 = (rowBase >> 4) + warpM * 4;     // first m16 tile of this warp

    // fragment gmem bases for this lane
    const char* af = (const char*)g_AhF + (size_t)tm0 * 512 + lid * 16;
    const char* wf = (const char*)g_WhF + (size_t)(cb * 16 + warpN * 4) * 1024 + lid * 32;

    uint32_t ab[2][16], bb[2][8];
    auto ldA = [&](int step, int buf) {
        const char* p = af + (size_t)step * 262144;          // 512 tiles * 512B
        #pragma unroll
        for (int mt = 0; mt < 4; mt++) {
            uint4 u = *(const uint4*)(p + mt * 512);
            ab[buf][mt * 4 + 0] = u.x; ab[buf][mt * 4 + 1] = u.y;
            ab[buf][mt * 4 + 2] = u.z; ab[buf][mt * 4 + 3] = u.w;
        }
    };
    auto ldB = [&](int step, int buf) {
        const char* p = wf + (size_t)(step >> 2) * 262144 + (size_t)(step & 3) * 1024;
        uint4 u0 = *(const uint4*)p;
        uint4 u1 = *(const uint4*)(p + 16);
        bb[buf][0] = u0.x; bb[buf][1] = u0.y; bb[buf][2] = u0.z; bb[buf][3] = u0.w;
        bb[buf][4] = u1.x; bb[buf][5] = u1.y; bb[buf][6] = u1.z; bb[buf][7] = u1.w;
    };

    ldA(0, 0); ldB(0, 0);

    float acc[4][4][4];
    #pragma unroll
    for (int i = 0; i < 4; i++)
        #pragma unroll
        for (int j = 0; j < 4; j++)
            #pragma unroll
            for (int k = 0; k < 4; k++) acc[i][j][k] = 0.f;

    #pragma unroll 1
    for (int s = 0; s < NSTEP; s += 2) {
        // buffer 0 holds step s; prefetch s+1 into buffer 1
        ldA(s + 1, 1); ldB(s + 1, 1);
        #pragma unroll
        for (int mt = 0; mt < 4; mt++)
            #pragma unroll
            for (int nt = 0; nt < 4; nt++)
                MMA_F16(acc[mt][nt], (ab[0] + mt * 4), (bb[0] + nt * 2));
        // prefetch s+2 into buffer 0
        if (s + 2 < NSTEP) { ldA(s + 2, 0); ldB(s + 2, 0); }
        #pragma unroll
        for (int mt = 0; mt < 4; mt++)
            #pragma unroll
            for (int nt = 0; nt < 4; nt++)
                MMA_F16(acc[mt][nt], (ab[1] + mt * 4), (bb[1] + nt * 2));
    }

    // ---- epilogue: bias -> relu -> mw*zeta -> relu ----
    const float zeta = g_zeta;
    const float mwz0 = mw[0] * zeta;
    const float mwz1 = mw[1] * zeta;

    #pragma unroll
    for (int nt = 0; nt < 4; nt++) {
        const int cLoc = warpN * 32 + nt * 8 + 2 * (lid & 3);
        const float b0 = bt[colBase + cLoc];
        const float b1 = bt[colBase + cLoc + 1];
        #pragma unroll
        for (int mt = 0; mt < 4; mt++) {
            const int m0 = rowBase + warpM * 64 + mt * 16 + (lid >> 2);
            const float mz = (m0 & 1) ? mwz1 : mwz0;
            float2 o0, o1;
            o0.x = fmaxf(mz * fmaxf(acc[mt][nt][0] + b0, 0.f), 0.f);
            o0.y = fmaxf(mz * fmaxf(acc[mt][nt][1] + b1, 0.f), 0.f);
            o1.x = fmaxf(mz * fmaxf(acc[mt][nt][2] + b0, 0.f), 0.f);
            o1.y = fmaxf(mz * fmaxf(acc[mt][nt][3] + b1, 0.f), 0.f);
            float* p0 = out + (size_t)m0 * DIM + colBase + cLoc;
            *(float2*)p0 = o0;
            *(float2*)(p0 + (size_t)8 * DIM) = o1;
        }
    }
}

// ---------------- launch ----------------
extern "C" void kernel_launch(void* const* d_in, const int* in_sizes, int n_in,
                              void* d_out, int out_size) {
    const float* x   = (const float*)d_in[0];
    const int*   ids = (const int*)  d_in[1];
    const float* mw  = (const float*)d_in[2];
    const float* emb = (const float*)d_in[3];
    const float* Wt  = (const float*)d_in[4];
    const float* bt  = (const float*)d_in[5];
    const float* Wrc = (const float*)d_in[6];
    const float* brc = (const float*)d_in[7];

    prep_all<<<ABLK + WFBLK + 1, 512>>>(x, ids, emb, Wt, Wrc, brc);

    dim3 grid(DIM / BN, NROWS / BM);   // (16, 64) = 1024 CTAs
    redaf_mma<<<grid, 256>>>(mw, bt, (float*)d_out);
}

// round 14
// speedup vs baseline: 1.0363x; 1.0363x over previous
#include <cuda_runtime.h>
#include <cuda_fp16.h>
#include <cstdint>

#define REL_CONTEXT 0.2f

// ---------------- problem dims (fixed) ----------------
#define NROWS 8192
#define DIM   2048
#define BM    128
#define BN    128
#define BK    64
#define KCH   16               // chunks per K-half
#define NSTAGE 4
#define NTILE  1024

// ---------------- scratch ----------------
__device__ __align__(128) __half g_Ah[(size_t)NROWS * DIM];
// W fragment-major (round-9 layout): group = ((ch*16+cb)*4+wN)*4+ks, 1024B each
__device__ __align__(128) uint32_t g_WhF[(size_t)DIM * DIM / 2];
__device__ __align__(128) float g_part[(size_t)NROWS * DIM];   // split-K partials
__device__ int g_flags[NTILE];
__device__ float g_zeta;

// ---------------- PTX helpers (base-target only) ----------------
__device__ __forceinline__ uint32_t smem_to_u32(const void* p) {
    uint32_t a;
    asm("{ .reg .u64 t; cvta.to.shared.u64 t, %1; cvt.u32.u64 %0, t; }"
        : "=r"(a) : "l"(p));
    return a;
}
#define MBARRIER_INIT(addr, cnt) \
    asm volatile("mbarrier.init.shared.b64 [%0], %1;" :: "r"((uint32_t)(addr)), "r"((uint32_t)(cnt)) : "memory")
#define MBARRIER_ARRIVE(addr) \
    asm volatile("mbarrier.arrive.shared.b64 _, [%0];" :: "r"((uint32_t)(addr)) : "memory")
#define MBARRIER_EXPECT_TX(addr, bytes) \
    asm volatile("mbarrier.arrive.expect_tx.shared.b64 _, [%0], %1;" \
                 :: "r"((uint32_t)(addr)), "r"((uint32_t)(bytes)) : "memory")
#define MBARRIER_WAIT_PARITY(addr, par) do { \
    uint32_t _m = (uint32_t)(addr); uint32_t _p = (uint32_t)(par); uint32_t _d; \
    asm volatile("{\n\t.reg .pred p;\n\t" \
        "mbarrier.try_wait.parity.acquire.cta.shared::cta.b64 p, [%1], %2;\n\t" \
        "selp.b32 %0, 1, 0, p;\n\t}" : "=r"(_d) : "r"(_m), "r"(_p) : "memory"); \
    if (!_d) { \
        asm volatile("{\n\t.reg .pred P1;\n\t" \
            "WL_%=:\n\t" \
            "mbarrier.try_wait.parity.acquire.cta.shared::cta.b64 P1, [%0], %1, 0x989680;\n\t" \
            "@P1 bra.uni WD_%=;\n\tbra.uni WL_%=;\n\tWD_%=:\n\t}" \
            :: "r"(_m), "r"(_p) : "memory"); \
    } } while (0)
#define BULK_G2S(dst, src, bytes, mbar) \
    asm volatile("cp.async.bulk.shared::cluster.global.mbarrier::complete_tx::bytes " \
                 "[%0], [%1], %2, [%3];" \
                 :: "r"((uint32_t)(dst)), "l"(src), "r"((uint32_t)(bytes)), \
                    "r"((uint32_t)(mbar)) : "memory")
#define LDMATRIX_X4(r0, r1, r2, r3, addr) \
    asm volatile("ldmatrix.sync.aligned.m8n8.x4.shared.b16 {%0,%1,%2,%3}, [%4];" \
                 : "=r"(r0), "=r"(r1), "=r"(r2), "=r"(r3) : "r"(addr))
#define MMA_F16(d, a, b) \
    asm volatile("mma.sync.aligned.m16n8k16.row.col.f32.f16.f16.f32 " \
                 "{%0,%1,%2,%3}, {%4,%5,%6,%7}, {%8,%9}, {%0,%1,%2,%3};" \
                 : "+f"((d)[0]), "+f"((d)[1]), "+f"((d)[2]), "+f"((d)[3]) \
                 : "r"((a)[0]), "r"((a)[1]), "r"((a)[2]), "r"((a)[3]), \
                   "r"((b)[0]), "r"((b)[1]))

// ---------------- smem layout ----------------
#define SM_BAR   0                    // full[s] at 16*s, empty[s] at 16*s+8
#define SM_BIAS  128                  // 128 floats
#define SM_TILES 1024
#define STAGE_BYTES 16384             // A tile only
#define SMEM_TOTAL (SM_TILES + NSTAGE * STAGE_BYTES)   // 66560 (2 CTAs/SM)

// 64-chunk-major, swizzled byte offset for (row, k0): 4 consecutive halves (8B)
__device__ __forceinline__ size_t scratch_off(int nTotRows, int row, int k0) {
    const int chunk = k0 >> 6;
    const int kc = k0 & 63;
    const int ci = kc >> 3;
    const int h8 = (kc >> 2) & 1;
    return ((size_t)chunk * nTotRows + row) * 128 + ((ci ^ (row & 7)) << 4) + h8 * 8;
}

__device__ __forceinline__ uint2 pack_h4(const float v[4]) {
    uint16_t h[4];
    #pragma unroll
    for (int i = 0; i < 4; i++) {
        __half hv = __float2half_rn(v[i]);
        h[i] = *(uint16_t*)&hv;
    }
    return make_uint2((uint32_t)h[0] | ((uint32_t)h[1] << 16),
                      (uint32_t)h[2] | ((uint32_t)h[3] << 16));
}

__device__ __forceinline__ uint32_t pack_h2(float a, float b) {
    __half ha = __float2half_rn(a), hb = __float2half_rn(b);
    return (uint32_t)*(uint16_t*)&ha | ((uint32_t)*(uint16_t*)&hb << 16);
}

// ---------------- merged prep kernel (round-9 proven + flag reset) -------
#define XBLK  (NROWS / 4)       // 2048 blocks: x+emb -> g_Ah (4 rows/block)
#define WGRPS (32 * 16 * 4 * 4) // 8192 fragment groups
#define WFBLK (WGRPS / 8)       // 1024 blocks: Wt -> g_WhF (8 groups/block)
__global__ void prep_all(const float* __restrict__ x,
                         const int* __restrict__ ids,
                         const float* __restrict__ emb,
                         const float* __restrict__ Wt,
                         const float* __restrict__ Wrc,
                         const float* __restrict__ brc) {
    const int b = blockIdx.x;
    const int c4 = threadIdx.x;           // 512 threads
    if (b < XBLK) {
        const int row0 = b * 4;
        float4 xv[4], ev[4];
        int id[4];
        #pragma unroll
        for (int r = 0; r < 4; r++) {
            id[r] = ids[row0 + r];
            xv[r] = ((const float4*)(x + (size_t)(row0 + r) * DIM))[c4];
        }
        #pragma unroll
        for (int r = 0; r < 4; r++)
            ev[r] = ((const float4*)(emb + (size_t)id[r] * DIM))[c4];
        #pragma unroll
        for (int r = 0; r < 4; r++) {
            float v[4] = {xv[r].x + ev[r].x, xv[r].y + ev[r].y,
                          xv[r].z + ev[r].z, xv[r].w + ev[r].w};
            *(uint2*)((char*)g_Ah + scratch_off(NROWS, row0 + r, c4 * 4)) = pack_h4(v);
        }
    } else if (b < XBLK + WFBLK) {
        const int g = (b - XBLK) * 8 + (c4 >> 6);
        const int t = c4 & 63;
        const int ks = g & 3;
        const int wN = (g >> 2) & 3;
        const int cb = (g >> 4) & 15;
        const int ch = g >> 8;
        const int lane = t >> 1;
        const int half = t & 1;
        const int n0 = cb * 128 + wN * 32 + half * 16 + (lane >> 2);
        const int k0 = ch * 64 + ks * 16 + (lane & 3) * 2;
        uint32_t w[4];
        #pragma unroll
        for (int dq = 0; dq < 2; dq++) {
            #pragma unroll
            for (int i = 0; i < 2; i++) {
                const float* p = Wt + (size_t)(n0 + dq * 8) * DIM + k0 + i * 8;
                float2 wv = *(const float2*)p;
                w[dq * 2 + i] = pack_h2(wv.x, wv.y);
            }
        }
        *(uint4*)((char*)g_WhF + (size_t)g * 1024 + lane * 32 + half * 16) =
            make_uint4(w[0], w[1], w[2], w[3]);
    } else {
        // flag reset (graph-replay safe) + zeta
        for (int i = c4; i < NTILE; i += 512) g_flags[i] = 0;
        __shared__ float red[32];
        float s = 0.f;
        for (int i = c4; i < DIM; i += 512) s += Wrc[i];
        #pragma unroll
        for (int o = 16; o > 0; o >>= 1) s += __shfl_down_sync(0xffffffffu, s, o);
        if ((c4 & 31) == 0) red[c4 >> 5] = s;
        __syncthreads();
        if (c4 < 32) {
            float v = (c4 < 16) ? red[c4] : 0.f;
            #pragma unroll
            for (int o = 8; o > 0; o >>= 1) v += __shfl_down_sync(0xffffffffu, v, o);
            if (c4 == 0)
                g_zeta = 1.f / (1.f + expf(-(REL_CONTEXT * v + brc[0])));
        }
    }
}

// ---------------- main MMA kernel: split-K=2 -----------------------------
__global__ __launch_bounds__(256, 2)
void redaf_mma(const float* __restrict__ mw,
               const float* __restrict__ bt,
               float* __restrict__ out) {
    extern __shared__ char smem[];
    const uint32_t sb = smem_to_u32(smem);
    const int tid = threadIdx.x;
    const int wid = tid >> 5;
    const int lid = tid & 31;

    const int cb      = blockIdx.x;        // col block (BN=128)
    const int colBase = cb * BN;
    const int rowBase = blockIdx.y * BM;
    const int kh      = blockIdx.z;        // K-half (0 or 1)
    const int tileId  = blockIdx.y * 16 + cb;

    if (tid == 0) {
        #pragma unroll
        for (int s = 0; s < NSTAGE; s++) {
            MBARRIER_INIT(sb + SM_BAR + 16 * s, 1);        // full: expect_tx
            MBARRIER_INIT(sb + SM_BAR + 16 * s + 8, 8);    // empty: 8 warps
        }
    }
    if (tid < BN) ((float*)(smem + SM_BIAS))[tid] = bt[colBase + tid];
    __syncthreads();

    // ---- producer: ONE 16KB bulk copy (A) per chunk (global chunk kh*16+c) ----
    auto produce = [&](int c) {
        const int s = c & 3;
        const uint32_t fb = sb + SM_BAR + 16 * s;
        MBARRIER_EXPECT_TX(fb, STAGE_BYTES);
        BULK_G2S(sb + SM_TILES + s * STAGE_BYTES,
                 (const char*)g_Ah + ((size_t)(kh * KCH + c) * NROWS + rowBase) * 128,
                 16384, fb);
    };

    // prefill chunks 0..2 into stages 0..2 (chunk 3 produced in iteration 0)
    if (lid == 0 && wid < NSTAGE - 1) produce(wid);

    // ---- warp grid 2(M) x 4(N); warp tile 64x32 (round-9 proven) ----
    const int warpM = wid & 1;
    const int warpN = wid >> 1;
    const int aRowL = warpM * 64 + (lid & 15);
    const int aKhalf = lid >> 4;

    // B fragment gmem base for this (cb, warpN, lane)
    const char* wf = (const char*)g_WhF + (size_t)(cb * 16 + warpN * 4) * 1024 + lid * 32;

    uint32_t bb[2][8];
    auto ldB = [&](int gstep, int buf) {     // gstep: global 16-wide k-step (0..127)
        const char* p = wf + (size_t)(gstep >> 2) * 262144 + (size_t)(gstep & 3) * 1024;
        uint4 u0 = *(const uint4*)p;
        uint4 u1 = *(const uint4*)(p + 16);
        bb[buf][0] = u0.x; bb[buf][1] = u0.y; bb[buf][2] = u0.z; bb[buf][3] = u0.w;
        bb[buf][4] = u1.x; bb[buf][5] = u1.y; bb[buf][6] = u1.z; bb[buf][7] = u1.w;
    };
    ldB(kh * 64, 0);                         // preload first step of this half

    float acc[4][4][4];
    #pragma unroll
    for (int i = 0; i < 4; i++)
        #pragma unroll
        for (int j = 0; j < 4; j++)
            #pragma unroll
            for (int k = 0; k < 4; k++) acc[i][j][k] = 0.f;

    #pragma unroll 1
    for (int c = 0; c < KCH; c++) {
        const int s = c & 3;
        const uint32_t par = (c >> 2) & 1;
        const uint32_t fullB = sb + SM_BAR + 16 * s;
        const uint32_t emptyB = fullB + 8;
        MBARRIER_WAIT_PARITY(fullB, par);

        const uint32_t stBase = sb + SM_TILES + s * STAGE_BYTES;
        #pragma unroll
        for (int ks = 0; ks < BK / 16; ks++) {
            const int cur = ks & 1;
            if (c < KCH - 1 || ks < 3) ldB(kh * 64 + c * 4 + ks + 1, cur ^ 1);
            uint32_t ah[4][4];
            #pragma unroll
            for (int mt = 0; mt < 4; mt++) {
                const int row = aRowL + mt * 16;
                const int ch = 2 * ks + aKhalf;
                const uint32_t off = row * 128 + ((ch ^ (row & 7)) << 4);
                LDMATRIX_X4(ah[mt][0], ah[mt][1], ah[mt][2], ah[mt][3],
                            stBase + off);
            }
            #pragma unroll
            for (int mt = 0; mt < 4; mt++)
                #pragma unroll
                for (int nt = 0; nt < 4; nt++)
                    MMA_F16(acc[mt][nt], ah[mt], (bb[cur] + nt * 2));
        }

        if (lid == 0) {
            MBARRIER_ARRIVE(emptyB);                  // this warp done reading chunk c
            const int t = (c + 3) & 3;
            if (wid == t && c + 3 < KCH) {
                if (c + 3 >= NSTAGE) {                // stage t had prior readers
                    MBARRIER_WAIT_PARITY(sb + SM_BAR + 16 * t + 8,
                                         (uint32_t)(((c - 1) >> 2) & 1));
                }
                produce(c + 3);
            }
        }
    }

    // ---- epilogue ----
    if (kh == 0) {
        // write raw partials, then release flag
        #pragma unroll
        for (int mt = 0; mt < 4; mt++) {
            #pragma unroll
            for (int nt = 0; nt < 4; nt++) {
                const int m0 = rowBase + warpM * 64 + mt * 16 + (lid >> 2);
                const int cLoc = warpN * 32 + nt * 8 + 2 * (lid & 3);
                float* p0 = g_part + (size_t)m0 * DIM + colBase + cLoc;
                *(float2*)p0 = make_float2(acc[mt][nt][0], acc[mt][nt][1]);
                *(float2*)(p0 + (size_t)8 * DIM) =
                    make_float2(acc[mt][nt][2], acc[mt][nt][3]);
            }
        }
        __syncthreads();
        if (tid == 0) {
            __threadfence();
            *(volatile int*)&g_flags[tileId] = 1;
        }
    } else {
        // acquire partner's partials, combine, apply bias/relu/gate/relu
        if (tid == 0) {
            while (*(volatile int*)&g_flags[tileId] == 0) __nanosleep(64);
            __threadfence();
        }
        __syncthreads();

        const float zeta = g_zeta;
        const float mwz0 = mw[0] * zeta;
        const float mwz1 = mw[1] * zeta;
        const float* bsm = (const float*)(smem + SM_BIAS);

        #pragma unroll
        for (int mt = 0; mt < 4; mt++) {
            #pragma unroll
            for (int nt = 0; nt < 4; nt++) {
                const int m0 = rowBase + warpM * 64 + mt * 16 + (lid >> 2);
                const int cLoc = warpN * 32 + nt * 8 + 2 * (lid & 3);
                const float b0 = bsm[cLoc], b1 = bsm[cLoc + 1];
                const float mz = (m0 & 1) ? mwz1 : mwz0;
                const float* pp = g_part + (size_t)m0 * DIM + colBase + cLoc;
                float2 q0 = *(const float2*)pp;
                float2 q1 = *(const float2*)(pp + (size_t)8 * DIM);
                float2 o0, o1;
                o0.x = fmaxf(mz * fmaxf(acc[mt][nt][0] + q0.x + b0, 0.f), 0.f);
                o0.y = fmaxf(mz * fmaxf(acc[mt][nt][1] + q0.y + b1, 0.f), 0.f);
                o1.x = fmaxf(mz * fmaxf(acc[mt][nt][2] + q1.x + b0, 0.f), 0.f);
                o1.y = fmaxf(mz * fmaxf(acc[mt][nt][3] + q1.y + b1, 0.f), 0.f);
                float* p0 = out + (size_t)m0 * DIM + colBase + cLoc;
                *(float2*)p0 = o0;
                *(float2*)(p0 + (size_t)8 * DIM) = o1;
            }
        }
    }
}

// ---------------- launch ----------------
extern "C" void kernel_launch(void* const* d_in, const int* in_sizes, int n_in,
                              void* d_out, int out_size) {
    const float* x   = (const float*)d_in[0];
    const int*   ids = (const int*)  d_in[1];
    const float* mw  = (const float*)d_in[2];
    const float* emb = (const float*)d_in[3];
    const float* Wt  = (const float*)d_in[4];
    const float* bt  = (const float*)d_in[5];
    const float* Wrc = (const float*)d_in[6];
    const float* brc = (const float*)d_in[7];

    cudaFuncSetAttribute(redaf_mma, cudaFuncAttributeMaxDynamicSharedMemorySize,
                         SMEM_TOTAL);

    prep_all<<<XBLK + WFBLK + 1, 512>>>(x, ids, emb, Wt, Wrc, brc);

    dim3 grid(DIM / BN, NROWS / BM, 2);   // (16, 64, 2) = 2048 CTAs
    redaf_mma<<<grid, 256, SMEM_TOTAL>>>(mw, bt, (float*)d_out);
}

// round 15
// speedup vs baseline: 1.1552x; 1.1147x over previous
#include <cuda_runtime.h>
#include <cuda_fp16.h>
#include <cstdint>

#define REL_CONTEXT 0.2f

// ---------------- problem dims (fixed) ----------------
#define NROWS 8192
#define DIM   2048
#define BN    128
#define BK    64
#define NCH   (DIM / BK)       // 32
#define NSTAGE 4
#define NTILE  1024
#define FULLT  888             // full 128-row tiles (~3 crisp waves of 296)
#define NHALF  ((NTILE - FULLT) * 2)   // 272 half tiles (64 rows each)

// ---------------- scratch ----------------
__device__ __align__(128) __half g_Ah[(size_t)NROWS * DIM];
// W fragment-major (round-9 layout): group = ((ch*16+cb)*4+wN)*4+ks, 1024B each
__device__ __align__(128) uint32_t g_WhF[(size_t)DIM * DIM / 2];
__device__ float g_zeta;

// ---------------- PTX helpers (base-target only) ----------------
__device__ __forceinline__ uint32_t smem_to_u32(const void* p) {
    uint32_t a;
    asm("{ .reg .u64 t; cvta.to.shared.u64 t, %1; cvt.u32.u64 %0, t; }"
        : "=r"(a) : "l"(p));
    return a;
}
#define MBARRIER_INIT(addr, cnt) \
    asm volatile("mbarrier.init.shared.b64 [%0], %1;" :: "r"((uint32_t)(addr)), "r"((uint32_t)(cnt)) : "memory")
#define MBARRIER_ARRIVE(addr) \
    asm volatile("mbarrier.arrive.shared.b64 _, [%0];" :: "r"((uint32_t)(addr)) : "memory")
#define MBARRIER_EXPECT_TX(addr, bytes) \
    asm volatile("mbarrier.arrive.expect_tx.shared.b64 _, [%0], %1;" \
                 :: "r"((uint32_t)(addr)), "r"((uint32_t)(bytes)) : "memory")
#define MBARRIER_WAIT_PARITY(addr, par) do { \
    uint32_t _m = (uint32_t)(addr); uint32_t _p = (uint32_t)(par); uint32_t _d; \
    asm volatile("{\n\t.reg .pred p;\n\t" \
        "mbarrier.try_wait.parity.acquire.cta.shared::cta.b64 p, [%1], %2;\n\t" \
        "selp.b32 %0, 1, 0, p;\n\t}" : "=r"(_d) : "r"(_m), "r"(_p) : "memory"); \
    if (!_d) { \
        asm volatile("{\n\t.reg .pred P1;\n\t" \
            "WL_%=:\n\t" \
            "mbarrier.try_wait.parity.acquire.cta.shared::cta.b64 P1, [%0], %1, 0x989680;\n\t" \
            "@P1 bra.uni WD_%=;\n\tbra.uni WL_%=;\n\tWD_%=:\n\t}" \
            :: "r"(_m), "r"(_p) : "memory"); \
    } } while (0)
#define BULK_G2S(dst, src, bytes, mbar) \
    asm volatile("cp.async.bulk.shared::cluster.global.mbarrier::complete_tx::bytes " \
                 "[%0], [%1], %2, [%3];" \
                 :: "r"((uint32_t)(dst)), "l"(src), "r"((uint32_t)(bytes)), \
                    "r"((uint32_t)(mbar)) : "memory")
#define LDMATRIX_X4(r0, r1, r2, r3, addr) \
    asm volatile("ldmatrix.sync.aligned.m8n8.x4.shared.b16 {%0,%1,%2,%3}, [%4];" \
                 : "=r"(r0), "=r"(r1), "=r"(r2), "=r"(r3) : "r"(addr))
#define MMA_F16(d, a, b) \
    asm volatile("mma.sync.aligned.m16n8k16.row.col.f32.f16.f16.f32 " \
                 "{%0,%1,%2,%3}, {%4,%5,%6,%7}, {%8,%9}, {%0,%1,%2,%3};" \
                 : "+f"((d)[0]), "+f"((d)[1]), "+f"((d)[2]), "+f"((d)[3]) \
                 : "r"((a)[0]), "r"((a)[1]), "r"((a)[2]), "r"((a)[3]), \
                   "r"((b)[0]), "r"((b)[1]))

// ---------------- smem layout ----------------
#define SM_BAR   0                    // full[s] at 16*s, empty[s] at 16*s+8
#define SM_BIAS  128                  // 128 floats
#define SM_TILES 1024
#define STAGE_BYTES 16384             // A tile slot (half path uses first 8KB)
#define SMEM_TOTAL (SM_TILES + NSTAGE * STAGE_BYTES)   // 66560 (2 CTAs/SM)

// 64-chunk-major, swizzled byte offset for (row, k0): 4 consecutive halves (8B)
__device__ __forceinline__ size_t scratch_off(int nTotRows, int row, int k0) {
    const int chunk = k0 >> 6;
    const int kc = k0 & 63;
    const int ci = kc >> 3;
    const int h8 = (kc >> 2) & 1;
    return ((size_t)chunk * nTotRows + row) * 128 + ((ci ^ (row & 7)) << 4) + h8 * 8;
}

__device__ __forceinline__ uint2 pack_h4(const float v[4]) {
    uint16_t h[4];
    #pragma unroll
    for (int i = 0; i < 4; i++) {
        __half hv = __float2half_rn(v[i]);
        h[i] = *(uint16_t*)&hv;
    }
    return make_uint2((uint32_t)h[0] | ((uint32_t)h[1] << 16),
                      (uint32_t)h[2] | ((uint32_t)h[3] << 16));
}

__device__ __forceinline__ uint32_t pack_h2(float a, float b) {
    __half ha = __float2half_rn(a), hb = __float2half_rn(b);
    return (uint32_t)*(uint16_t*)&ha | ((uint32_t)*(uint16_t*)&hb << 16);
}

// ---------------- merged prep kernel (round-9 proven, unchanged) --------
#define XBLK  (NROWS / 4)       // 2048 blocks: x+emb -> g_Ah (4 rows/block)
#define WGRPS (32 * 16 * 4 * 4) // 8192 fragment groups
#define WFBLK (WGRPS / 8)       // 1024 blocks: Wt -> g_WhF (8 groups/block)
__global__ void prep_all(const float* __restrict__ x,
                         const int* __restrict__ ids,
                         const float* __restrict__ emb,
                         const float* __restrict__ Wt,
                         const float* __restrict__ Wrc,
                         const float* __restrict__ brc) {
    const int b = blockIdx.x;
    const int c4 = threadIdx.x;           // 512 threads
    if (b < XBLK) {
        const int row0 = b * 4;
        float4 xv[4], ev[4];
        int id[4];
        #pragma unroll
        for (int r = 0; r < 4; r++) {
            id[r] = ids[row0 + r];
            xv[r] = ((const float4*)(x + (size_t)(row0 + r) * DIM))[c4];
        }
        #pragma unroll
        for (int r = 0; r < 4; r++)
            ev[r] = ((const float4*)(emb + (size_t)id[r] * DIM))[c4];
        #pragma unroll
        for (int r = 0; r < 4; r++) {
            float v[4] = {xv[r].x + ev[r].x, xv[r].y + ev[r].y,
                          xv[r].z + ev[r].z, xv[r].w + ev[r].w};
            *(uint2*)((char*)g_Ah + scratch_off(NROWS, row0 + r, c4 * 4)) = pack_h4(v);
        }
    } else if (b < XBLK + WFBLK) {
        const int g = (b - XBLK) * 8 + (c4 >> 6);
        const int t = c4 & 63;
        const int ks = g & 3;
        const int wN = (g >> 2) & 3;
        const int cb = (g >> 4) & 15;
        const int ch = g >> 8;
        const int lane = t >> 1;
        const int half = t & 1;
        const int n0 = cb * 128 + wN * 32 + half * 16 + (lane >> 2);
        const int k0 = ch * 64 + ks * 16 + (lane & 3) * 2;
        uint32_t w[4];
        #pragma unroll
        for (int dq = 0; dq < 2; dq++) {
            #pragma unroll
            for (int i = 0; i < 2; i++) {
                const float* p = Wt + (size_t)(n0 + dq * 8) * DIM + k0 + i * 8;
                float2 wv = *(const float2*)p;
                w[dq * 2 + i] = pack_h2(wv.x, wv.y);
            }
        }
        *(uint4*)((char*)g_WhF + (size_t)g * 1024 + lane * 32 + half * 16) =
            make_uint4(w[0], w[1], w[2], w[3]);
    } else {
        __shared__ float red[32];
        float s = 0.f;
        for (int i = c4; i < DIM; i += 512) s += Wrc[i];
        #pragma unroll
        for (int o = 16; o > 0; o >>= 1) s += __shfl_down_sync(0xffffffffu, s, o);
        if ((c4 & 31) == 0) red[c4 >> 5] = s;
        __syncthreads();
        if (c4 < 32) {
            float v = (c4 < 16) ? red[c4] : 0.f;
            #pragma unroll
            for (int o = 8; o > 0; o >>= 1) v += __shfl_down_sync(0xffffffffu, v, o);
            if (c4 == 0)
                g_zeta = 1.f / (1.f + expf(-(REL_CONTEXT * v + brc[0])));
        }
    }
}

// ---------------- GEMM tile path, templated on M-tile count -------------
// MT=4: 128-row tile (round-9 exact). MT=2: 64-row half tile.
template <int MT>
__device__ __forceinline__ void gemm_tile(const float* __restrict__ mw,
                                          float* __restrict__ out,
                                          char* smem, uint32_t sb,
                                          int tid, int wid, int lid,
                                          int rowBase, int colBase, int cb) {
    constexpr uint32_t TILEB = MT * 4096;     // A-tile bytes per chunk

    // ---- producer: ONE bulk copy (A) per chunk ----
    auto produce = [&](int c) {
        const int s = c & 3;
        const uint32_t fb = sb + SM_BAR + 16 * s;
        MBARRIER_EXPECT_TX(fb, TILEB);
        BULK_G2S(sb + SM_TILES + s * STAGE_BYTES,
                 (const char*)g_Ah + ((size_t)c * NROWS + rowBase) * 128, TILEB, fb);
    };
    if (lid == 0 && wid < NSTAGE - 1) produce(wid);

    // warp grid 2(M) x 4(N); warp tile (MT*16) x 32
    const int warpM = wid & 1;
    const int warpN = wid >> 1;
    const int aRowL = warpM * (MT * 16) + (lid & 15);
    const int aKhalf = lid >> 4;

    const char* wf = (const char*)g_WhF + (size_t)(cb * 16 + warpN * 4) * 1024 + lid * 32;
    uint32_t bb[2][8];
    auto ldB = [&](int step, int buf) {
        const char* p = wf + (size_t)(step >> 2) * 262144 + (size_t)(step & 3) * 1024;
        uint4 u0 = *(const uint4*)p;
        uint4 u1 = *(const uint4*)(p + 16);
        bb[buf][0] = u0.x; bb[buf][1] = u0.y; bb[buf][2] = u0.z; bb[buf][3] = u0.w;
        bb[buf][4] = u1.x; bb[buf][5] = u1.y; bb[buf][6] = u1.z; bb[buf][7] = u1.w;
    };
    ldB(0, 0);

    float acc[MT][4][4];
    #pragma unroll
    for (int i = 0; i < MT; i++)
        #pragma unroll
        for (int j = 0; j < 4; j++)
            #pragma unroll
            for (int k = 0; k < 4; k++) acc[i][j][k] = 0.f;

    #pragma unroll 1
    for (int c = 0; c < NCH; c++) {
        const int s = c & 3;
        const uint32_t par = (c >> 2) & 1;
        const uint32_t fullB = sb + SM_BAR + 16 * s;
        const uint32_t emptyB = fullB + 8;
        MBARRIER_WAIT_PARITY(fullB, par);

        const uint32_t stBase = sb + SM_TILES + s * STAGE_BYTES;
        #pragma unroll
        for (int ks = 0; ks < BK / 16; ks++) {
            const int cur = ks & 1;
            if (c < NCH - 1 || ks < 3) ldB(c * 4 + ks + 1, cur ^ 1);
            uint32_t ah[MT][4];
            #pragma unroll
            for (int mt = 0; mt < MT; mt++) {
                const int row = aRowL + mt * 16;
                const int ch = 2 * ks + aKhalf;
                const uint32_t off = row * 128 + ((ch ^ (row & 7)) << 4);
                LDMATRIX_X4(ah[mt][0], ah[mt][1], ah[mt][2], ah[mt][3],
                            stBase + off);
            }
            #pragma unroll
            for (int mt = 0; mt < MT; mt++)
                #pragma unroll
                for (int nt = 0; nt < 4; nt++)
                    MMA_F16(acc[mt][nt], ah[mt], (bb[cur] + nt * 2));
        }

        if (lid == 0) {
            MBARRIER_ARRIVE(emptyB);
            const int t = (c + 3) & 3;
            if (wid == t && c + 3 < NCH) {
                if (c + 3 >= NSTAGE) {
                    MBARRIER_WAIT_PARITY(sb + SM_BAR + 16 * t + 8,
                                         (uint32_t)(((c - 1) >> 2) & 1));
                }
                produce(c + 3);
            }
        }
    }

    // ---- epilogue: bias -> relu -> mw*zeta -> relu ----
    const float zeta = g_zeta;
    const float mwz0 = mw[0] * zeta;
    const float mwz1 = mw[1] * zeta;
    const float* bsm = (const float*)(smem + SM_BIAS);

    #pragma unroll
    for (int mt = 0; mt < MT; mt++) {
        #pragma unroll
        for (int nt = 0; nt < 4; nt++) {
            const int m0 = rowBase + warpM * (MT * 16) + mt * 16 + (lid >> 2);
            const int cLoc = warpN * 32 + nt * 8 + 2 * (lid & 3);
            const float b0 = bsm[cLoc], b1 = bsm[cLoc + 1];
            const float mz = (m0 & 1) ? mwz1 : mwz0;
            float2 o0, o1;
            o0.x = fmaxf(mz * fmaxf(acc[mt][nt][0] + b0, 0.f), 0.f);
            o0.y = fmaxf(mz * fmaxf(acc[mt][nt][1] + b1, 0.f), 0.f);
            o1.x = fmaxf(mz * fmaxf(acc[mt][nt][2] + b0, 0.f), 0.f);
            o1.y = fmaxf(mz * fmaxf(acc[mt][nt][3] + b1, 0.f), 0.f);
            float* p0 = out + (size_t)m0 * DIM + colBase + cLoc;
            *(float2*)p0 = o0;
            *(float2*)(p0 + (size_t)8 * DIM) = o1;
        }
    }
}

// ---------------- main kernel: 888 full tiles + 272 M-half tiles --------
__global__ __launch_bounds__(256, 2)
void redaf_mma(const float* __restrict__ mw,
               const float* __restrict__ bt,
               float* __restrict__ out) {
    extern __shared__ char smem[];
    const uint32_t sb = smem_to_u32(smem);
    const int tid = threadIdx.x;
    const int wid = tid >> 5;
    const int lid = tid & 31;
    const int b = blockIdx.x;

    int tileId, halfSel;
    if (b < FULLT) { tileId = b; halfSel = -1; }
    else {
        const int h = b - FULLT;
        tileId = FULLT + (h >> 1);
        halfSel = h & 1;
    }
    const int cb = tileId & 15;
    const int colBase = cb * BN;
    const int rowBase = (tileId >> 4) * 128 + (halfSel > 0 ? 64 : 0);

    if (tid == 0) {
        #pragma unroll
        for (int s = 0; s < NSTAGE; s++) {
            MBARRIER_INIT(sb + SM_BAR + 16 * s, 1);        // full: expect_tx
            MBARRIER_INIT(sb + SM_BAR + 16 * s + 8, 8);    // empty: 8 warps
        }
    }
    if (tid < BN) ((float*)(smem + SM_BIAS))[tid] = bt[colBase + tid];
    __syncthreads();

    if (halfSel < 0)
        gemm_tile<4>(mw, out, smem, sb, tid, wid, lid, rowBase, colBase, cb);
    else
        gemm_tile<2>(mw, out, smem, sb, tid, wid, lid, rowBase, colBase, cb);
}

// ---------------- launch ----------------
extern "C" void kernel_launch(void* const* d_in, const int* in_sizes, int n_in,
                              void* d_out, int out_size) {
    const float* x   = (const float*)d_in[0];
    const int*   ids = (const int*)  d_in[1];
    const float* mw  = (const float*)d_in[2];
    const float* emb = (const float*)d_in[3];
    const float* Wt  = (const float*)d_in[4];
    const float* bt  = (const float*)d_in[5];
    const float* Wrc = (const float*)d_in[6];
    const float* brc = (const float*)d_in[7];

    cudaFuncSetAttribute(redaf_mma, cudaFuncAttributeMaxDynamicSharedMemorySize,
                         SMEM_TOTAL);

    prep_all<<<XBLK + WFBLK + 1, 512>>>(x, ids, emb, Wt, Wrc, brc);

    redaf_mma<<<FULLT + NHALF, 256, SMEM_TOTAL>>>(mw, bt, (float*)d_out);
}

// round 16
// speedup vs baseline: 1.1868x; 1.0273x over previous
#include <cuda_runtime.h>
#include <cuda_fp16.h>
#include <cstdint>

#define REL_CONTEXT 0.2f

// ---------------- problem dims (fixed) ----------------
#define NROWS 8192
#define DIM   2048
#define BM    128
#define BN    128
#define BK    64
#define NCH   (DIM / BK)       // 32
#define NSTAGE 4

// ---------------- scratch ----------------
// A: 64-chunk-major, pre-swizzled fp16
__device__ __align__(128) __half g_Ah[(size_t)NROWS * DIM];
// W fragment-major (round-9 layout): group = ((ch*16+cb)*4+wN)*4+ks, 1024B each
__device__ __align__(128) uint32_t g_WhF[(size_t)DIM * DIM / 2];
__device__ float g_zeta;

// ---------------- PTX helpers (base-target only) ----------------
__device__ __forceinline__ uint32_t smem_to_u32(const void* p) {
    uint32_t a;
    asm("{ .reg .u64 t; cvta.to.shared.u64 t, %1; cvt.u32.u64 %0, t; }"
        : "=r"(a) : "l"(p));
    return a;
}
#define MBARRIER_INIT(addr, cnt) \
    asm volatile("mbarrier.init.shared.b64 [%0], %1;" :: "r"((uint32_t)(addr)), "r"((uint32_t)(cnt)) : "memory")
#define MBARRIER_ARRIVE(addr) \
    asm volatile("mbarrier.arrive.shared.b64 _, [%0];" :: "r"((uint32_t)(addr)) : "memory")
#define MBARRIER_EXPECT_TX(addr, bytes) \
    asm volatile("mbarrier.arrive.expect_tx.shared.b64 _, [%0], %1;" \
                 :: "r"((uint32_t)(addr)), "r"((uint32_t)(bytes)) : "memory")
#define MBARRIER_WAIT_PARITY(addr, par) do { \
    uint32_t _m = (uint32_t)(addr); uint32_t _p = (uint32_t)(par); uint32_t _d; \
    asm volatile("{\n\t.reg .pred p;\n\t" \
        "mbarrier.try_wait.parity.acquire.cta.shared::cta.b64 p, [%1], %2;\n\t" \
        "selp.b32 %0, 1, 0, p;\n\t}" : "=r"(_d) : "r"(_m), "r"(_p) : "memory"); \
    if (!_d) { \
        asm volatile("{\n\t.reg .pred P1;\n\t" \
            "WL_%=:\n\t" \
            "mbarrier.try_wait.parity.acquire.cta.shared::cta.b64 P1, [%0], %1, 0x989680;\n\t" \
            "@P1 bra.uni WD_%=;\n\tbra.uni WL_%=;\n\tWD_%=:\n\t}" \
            :: "r"(_m), "r"(_p) : "memory"); \
    } } while (0)
#define BULK_G2S(dst, src, bytes, mbar) \
    asm volatile("cp.async.bulk.shared::cluster.global.mbarrier::complete_tx::bytes " \
                 "[%0], [%1], %2, [%3];" \
                 :: "r"((uint32_t)(dst)), "l"(src), "r"((uint32_t)(bytes)), \
                    "r"((uint32_t)(mbar)) : "memory")
#define LDMATRIX_X4(r0, r1, r2, r3, addr) \
    asm volatile("ldmatrix.sync.aligned.m8n8.x4.shared.b16 {%0,%1,%2,%3}, [%4];" \
                 : "=r"(r0), "=r"(r1), "=r"(r2), "=r"(r3) : "r"(addr))
#define MMA_F16(d, a, b) \
    asm volatile("mma.sync.aligned.m16n8k16.row.col.f32.f16.f16.f32 " \
                 "{%0,%1,%2,%3}, {%4,%5,%6,%7}, {%8,%9}, {%0,%1,%2,%3};" \
                 : "+f"((d)[0]), "+f"((d)[1]), "+f"((d)[2]), "+f"((d)[3]) \
                 : "r"((a)[0]), "r"((a)[1]), "r"((a)[2]), "r"((a)[3]), \
                   "r"((b)[0]), "r"((b)[1]))

// ---------------- smem layout ----------------
#define SM_BAR   0                    // full[s] at 16*s, empty[s] at 16*s+8
#define SM_BIAS  128                  // 128 floats
#define SM_TILES 1024
#define STAGE_BYTES 16384             // A tile only
#define SMEM_TOTAL (SM_TILES + NSTAGE * STAGE_BYTES)   // 66560 (2 CTAs/SM)

__device__ __forceinline__ uint32_t pack_h2(float a, float b) {
    __half ha = __float2half_rn(a), hb = __float2half_rn(b);
    return (uint32_t)*(uint16_t*)&ha | ((uint32_t)*(uint16_t*)&hb << 16);
}

// ---------------- merged prep kernel -------------------------------------
// A path: one thread per 16B scratch chunk -> single STG.128
//   block b < ABLK handles rows b*2, b*2+1; thread t: r = t>>8, ci = t&255
#define ABLK  (NROWS / 2)       // 4096 blocks
#define WGRPS (32 * 16 * 4 * 4) // 8192 W fragment groups
#define WFBLK (WGRPS / 8)       // 1024 blocks
__global__ void prep_all(const float* __restrict__ x,
                         const int* __restrict__ ids,
                         const float* __restrict__ emb,
                         const float* __restrict__ Wt,
                         const float* __restrict__ Wrc,
                         const float* __restrict__ brc) {
    const int b = blockIdx.x;
    const int t = threadIdx.x;            // 512 threads
    if (b < ABLK) {
        const int row = b * 2 + (t >> 8);
        const int ci = t & 255;           // 16B chunk within row (0..255)
        const int k0 = ci * 8;            // first half index
        const int id = __ldg(&ids[row]);
        const float* xp = x + (size_t)row * DIM + k0;
        const float* ep = emb + (size_t)id * DIM + k0;
        float4 x0 = *(const float4*)xp;
        float4 x1 = *(const float4*)(xp + 4);
        float4 e0 = *(const float4*)ep;
        float4 e1 = *(const float4*)(ep + 4);
        uint4 o;
        o.x = pack_h2(x0.x + e0.x, x0.y + e0.y);
        o.y = pack_h2(x0.z + e0.z, x0.w + e0.w);
        o.z = pack_h2(x1.x + e1.x, x1.y + e1.y);
        o.w = pack_h2(x1.z + e1.z, x1.w + e1.w);
        // scratch offset: 64-half chunk = ci>>3; 16B slot = (ci&7) ^ (row&7)
        const int perm = (ci & 7) ^ (row & 7);
        const size_t off = ((size_t)(ci >> 3) * NROWS + row) * 128 + perm * 16;
        *(uint4*)((char*)g_Ah + off) = o;
    } else if (b < ABLK + WFBLK) {
        const int g = (b - ABLK) * 8 + (t >> 6);
        const int tt = t & 63;
        const int ks = g & 3;
        const int wN = (g >> 2) & 3;
        const int cb = (g >> 4) & 15;
        const int ch = g >> 8;
        const int lane = tt >> 1;
        const int half = tt & 1;
        const int n0 = cb * 128 + wN * 32 + half * 16 + (lane >> 2);
        const int k0 = ch * 64 + ks * 16 + (lane & 3) * 2;
        uint32_t w[4];
        #pragma unroll
        for (int dq = 0; dq < 2; dq++) {
            #pragma unroll
            for (int i = 0; i < 2; i++) {
                const float* p = Wt + (size_t)(n0 + dq * 8) * DIM + k0 + i * 8;
                float2 wv = *(const float2*)p;
                w[dq * 2 + i] = pack_h2(wv.x, wv.y);
            }
        }
        *(uint4*)((char*)g_WhF + (size_t)g * 1024 + lane * 32 + half * 16) =
            make_uint4(w[0], w[1], w[2], w[3]);
    } else {
        __shared__ float red[32];
        float s = 0.f;
        for (int i = t; i < DIM; i += 512) s += Wrc[i];
        #pragma unroll
        for (int o = 16; o > 0; o >>= 1) s += __shfl_down_sync(0xffffffffu, s, o);
        if ((t & 31) == 0) red[t >> 5] = s;
        __syncthreads();
        if (t < 32) {
            float v = (t < 16) ? red[t] : 0.f;
            #pragma unroll
            for (int o = 8; o > 0; o >>= 1) v += __shfl_down_sync(0xffffffffu, v, o);
            if (t == 0)
                g_zeta = 1.f / (1.f + expf(-(REL_CONTEXT * v + brc[0])));
        }
    }
}

// ---------------- main MMA kernel (round-9 proven, verbatim) -------------
__global__ __launch_bounds__(256, 2)
void redaf_mma(const float* __restrict__ mw,
               const float* __restrict__ bt,
               float* __restrict__ out) {
    extern __shared__ char smem[];
    const uint32_t sb = smem_to_u32(smem);
    const int tid = threadIdx.x;
    const int wid = tid >> 5;
    const int lid = tid & 31;

    const int cb      = blockIdx.x;        // col block (BN=128)
    const int colBase = cb * BN;
    const int rowBase = blockIdx.y * BM;

    if (tid == 0) {
        #pragma unroll
        for (int s = 0; s < NSTAGE; s++) {
            MBARRIER_INIT(sb + SM_BAR + 16 * s, 1);        // full: expect_tx
            MBARRIER_INIT(sb + SM_BAR + 16 * s + 8, 8);    // empty: 8 warps
        }
    }
    if (tid < BN) ((float*)(smem + SM_BIAS))[tid] = bt[colBase + tid];
    __syncthreads();

    // ---- producer: ONE 16KB bulk copy (A) per chunk ----
    auto produce = [&](int c) {
        const int s = c & 3;
        const uint32_t fb = sb + SM_BAR + 16 * s;
        MBARRIER_EXPECT_TX(fb, STAGE_BYTES);
        BULK_G2S(sb + SM_TILES + s * STAGE_BYTES,
                 (const char*)g_Ah + ((size_t)c * NROWS + rowBase) * 128, 16384, fb);
    };

    // prefill chunks 0..2 into stages 0..2 (chunk 3 produced in iteration 0)
    if (lid == 0 && wid < NSTAGE - 1) produce(wid);

    // ---- warp grid 2(M) x 4(N); warp tile 64x32 ----
    const int warpM = wid & 1;
    const int warpN = wid >> 1;
    const int aRowL = warpM * 64 + (lid & 15);
    const int aKhalf = lid >> 4;

    // B fragment gmem base for this (cb, warpN, lane)
    const char* wf = (const char*)g_WhF + (size_t)(cb * 16 + warpN * 4) * 1024 + lid * 32;

    uint32_t bb[2][8];
    auto ldB = [&](int step, int buf) {
        const char* p = wf + (size_t)(step >> 2) * 262144 + (size_t)(step & 3) * 1024;
        uint4 u0 = *(const uint4*)p;
        uint4 u1 = *(const uint4*)(p + 16);
        bb[buf][0] = u0.x; bb[buf][1] = u0.y; bb[buf][2] = u0.z; bb[buf][3] = u0.w;
        bb[buf][4] = u1.x; bb[buf][5] = u1.y; bb[buf][6] = u1.z; bb[buf][7] = u1.w;
    };
    ldB(0, 0);                      // preload step 0

    float acc[4][4][4];
    #pragma unroll
    for (int i = 0; i < 4; i++)
        #pragma unroll
        for (int j = 0; j < 4; j++)
            #pragma unroll
            for (int k = 0; k < 4; k++) acc[i][j][k] = 0.f;

    #pragma unroll 1
    for (int c = 0; c < NCH; c++) {
        const int s = c & 3;
        const uint32_t par = (c >> 2) & 1;
        const uint32_t fullB = sb + SM_BAR + 16 * s;
        const uint32_t emptyB = fullB + 8;
        MBARRIER_WAIT_PARITY(fullB, par);

        const uint32_t stBase = sb + SM_TILES + s * STAGE_BYTES;
        #pragma unroll
        for (int ks = 0; ks < BK / 16; ks++) {
            const int cur = ks & 1;
            if (c < NCH - 1 || ks < 3) ldB(c * 4 + ks + 1, cur ^ 1);
            uint32_t ah[4][4];
            #pragma unroll
            for (int mt = 0; mt < 4; mt++) {
                const int row = aRowL + mt * 16;
                const int ch = 2 * ks + aKhalf;
                const uint32_t off = row * 128 + ((ch ^ (row & 7)) << 4);
                LDMATRIX_X4(ah[mt][0], ah[mt][1], ah[mt][2], ah[mt][3],
                            stBase + off);
            }
            #pragma unroll
            for (int mt = 0; mt < 4; mt++)
                #pragma unroll
                for (int nt = 0; nt < 4; nt++)
                    MMA_F16(acc[mt][nt], ah[mt], (bb[cur] + nt * 2));
        }

        if (lid == 0) {
            MBARRIER_ARRIVE(emptyB);                // this warp done with chunk c
            const int t = (c + 3) & 3;
            if (wid == t && c + 3 < NCH) {
                if (c + 3 >= NSTAGE) {              // stage t had prior readers
                    MBARRIER_WAIT_PARITY(sb + SM_BAR + 16 * t + 8,
                                         (uint32_t)(((c - 1) >> 2) & 1));
                }
                produce(c + 3);
            }
        }
    }

    // ---- epilogue: bias -> relu -> mw*zeta -> relu ----
    const float zeta = g_zeta;
    const float mwz0 = mw[0] * zeta;
    const float mwz1 = mw[1] * zeta;
    const float* bsm = (const float*)(smem + SM_BIAS);

    #pragma unroll
    for (int mt = 0; mt < 4; mt++) {
        #pragma unroll
        for (int nt = 0; nt < 4; nt++) {
            const int m0 = rowBase + warpM * 64 + mt * 16 + (lid >> 2);
            const int cLoc = warpN * 32 + nt * 8 + 2 * (lid & 3);
            const float b0 = bsm[cLoc], b1 = bsm[cLoc + 1];
            const float mz = (m0 & 1) ? mwz1 : mwz0;
            float2 o0, o1;
            o0.x = fmaxf(mz * fmaxf(acc[mt][nt][0] + b0, 0.f), 0.f);
            o0.y = fmaxf(mz * fmaxf(acc[mt][nt][1] + b1, 0.f), 0.f);
            o1.x = fmaxf(mz * fmaxf(acc[mt][nt][2] + b0, 0.f), 0.f);
            o1.y = fmaxf(mz * fmaxf(acc[mt][nt][3] + b1, 0.f), 0.f);
            float* p0 = out + (size_t)m0 * DIM + colBase + cLoc;
            *(float2*)p0 = o0;
            *(float2*)(p0 + (size_t)8 * DIM) = o1;
        }
    }
}

// ---------------- launch ----------------
extern "C" void kernel_launch(void* const* d_in, const int* in_sizes, int n_in,
                              void* d_out, int out_size) {
    const float* x   = (const float*)d_in[0];
    const int*   ids = (const int*)  d_in[1];
    const float* mw  = (const float*)d_in[2];
    const float* emb = (const float*)d_in[3];
    const float* Wt  = (const float*)d_in[4];
    const float* bt  = (const float*)d_in[5];
    const float* Wrc = (const float*)d_in[6];
    const float* brc = (const float*)d_in[7];

    cudaFuncSetAttribute(redaf_mma, cudaFuncAttributeMaxDynamicSharedMemorySize,
                         SMEM_TOTAL);

    prep_all<<<ABLK + WFBLK + 1, 512>>>(x, ids, emb, Wt, Wrc, brc);

    dim3 grid(DIM / BN, NROWS / BM);   // (16, 64) = 1024 CTAs
    redaf_mma<<<grid, 256, SMEM_TOTAL>>>(mw, bt, (float*)d_out);
}